// round 3
// baseline (speedup 1.0000x reference)
#include <cuda_runtime.h>
#include <cstdint>
#include <cstddef>

#define BB 32
#define NN 25200
#define NCC 20
#define KK 1024
#define MAXDET 300
#define CONF_T 0.001f
#define IOU_T 0.45f

// ---------- scratch (static device allocations; no cudaMalloc) ----------
__device__ float         g_conf[BB * NN];
__device__ unsigned char g_lab [BB * NN];
__device__ float4        g_tbox[BB * KK];
__device__ float         g_tsc [BB * KK];
__device__ int           g_tlb [BB * KK];
__device__ unsigned      g_msk [BB * KK * 32];   // TRANSPOSED mask: [b][w*1024+j], bit bi => i=32w+bi suppresses j (i<j)

// ---------- kernel A: scores + argmax labels (memory-bound full read, float4) ----------
__global__ void k_score(const float* __restrict__ pred) {
    __shared__ float s[256 * 25];
    size_t base4 = (size_t)blockIdx.x * 1600;           // 6400 floats = 1600 float4
    const float4* p4 = (const float4*)pred + base4;
    float4* s4 = (float4*)s;
    for (int k = threadIdx.x; k < 1600; k += 256) s4[k] = p4[k];
    __syncthreads();
    const float* row = s + threadIdx.x * 25;
    float obj  = row[4];
    float best = row[5];
    int   bl   = 0;
#pragma unroll
    for (int c = 1; c < NCC; c++) {
        float v = row[5 + c];
        if (v > best) { best = v; bl = c; }  // first-max like jnp.argmax
    }
    float conf = __fmul_rn(obj, best);
    size_t r = (size_t)blockIdx.x * 256 + threadIdx.x;
    g_conf[r] = conf;
    g_lab[r]  = (unsigned char)bl;
}

// ---------- kernel B1: exact stable top-1024 per batch (bucket select + hybrid bitonic) ----------
__global__ void k_topk(const float* __restrict__ pred) {
    extern __shared__ unsigned sh[];
    unsigned* hist  = sh;                 // 32768 words (128 KB)
    unsigned* chunk = sh + 32768;         // 1024 words
    int*      ctrl  = (int*)(sh + 33792); // 16 words: [0]=cstar [1]=T [2]=cnt
    unsigned* wsc   = sh + 33808;         // 64 words: warp totals + tails
    unsigned long long* cand = (unsigned long long*)sh;  // overlays hist (8192 keys)

    int b = blockIdx.x;
    int tid = threadIdx.x;
    int lane = tid & 31, wid = tid >> 5;
    const float* sc = g_conf + (size_t)b * NN;

    for (int k = tid; k < 32768; k += 1024) hist[k] = 0;
    if (tid < 16) ctrl[tid] = (tid == 0) ? -1 : 0;
    __syncthreads();

    // pass 1: histogram of float bits >>15 (positive scores are order-preserving)
    for (int n = tid; n < NN; n += 1024) {
        float v = sc[n];
        if (v > CONF_T) atomicAdd(&hist[__float_as_uint(v) >> 15], 1u);
    }
    __syncthreads();

    // per-thread chunk sums, then suffix-scan via warp shuffles (2 bars, not 20)
    unsigned sum = 0;
    {
        unsigned* hb = hist + tid * 32;
#pragma unroll
        for (int q = 0; q < 32; q++) sum += hb[q];
    }
    unsigned s = sum;
#pragma unroll
    for (int off = 1; off < 32; off <<= 1) {
        unsigned v = __shfl_down_sync(0xffffffffu, s, off);
        if (lane + off < 32) s += v;
    }
    if (lane == 0) wsc[wid] = s;          // warp total (suffix at lane 0)
    __syncthreads();
    if (wid == 0) {
        unsigned t = wsc[lane];
#pragma unroll
        for (int off = 1; off < 32; off <<= 1) {
            unsigned v = __shfl_down_sync(0xffffffffu, t, off);
            if (lane + off < 32) t += v;
        }
        unsigned tail = __shfl_down_sync(0xffffffffu, t, 1);
        if (lane == 31) tail = 0;
        wsc[32 + lane] = tail;            // sum of totals of warps > lane
    }
    __syncthreads();
    unsigned csuf = s + wsc[32 + wid];
    chunk[tid] = csuf;
    if (csuf >= KK) atomicMax(&ctrl[0], tid);
    __syncthreads();
    if (tid == 0) {
        int cs = ctrl[0];
        int T = 0;
        if (cs >= 0) {
            unsigned running = (cs < 1023) ? chunk[cs + 1] : 0u;
            for (int bk = cs * 32 + 31; bk >= cs * 32; bk--) {
                running += hist[bk];
                if (running >= KK) { T = bk; break; }
            }
        }
        ctrl[1] = T;
        ctrl[2] = 0;
    }
    __syncthreads();
    unsigned T = (unsigned)ctrl[1];
    __syncthreads();   // hist reads done; cand may now overlay hist

    // pass 2: collect candidates with stable-tiebreak keys
    for (int n = tid; n < NN; n += 1024) {
        float v = sc[n];
        if (v > CONF_T && (__float_as_uint(v) >> 15) >= T) {
            int p = atomicAdd(&ctrl[2], 1);
            if (p < 8192)
                cand[p] = ((unsigned long long)__float_as_uint(v) << 32)
                        | (unsigned long long)(0xFFFFFFFFu - (unsigned)n);
        }
    }
    __syncthreads();
    int cnt = ctrl[2]; if (cnt > 8192) cnt = 8192;

    if (cnt <= 2048) {
        // ---- hybrid bitonic sort of 2048 keys, descending ----
        for (int p = cnt + tid; p < 2048; p += 1024) cand[p] = 0ull;
        __syncthreads();
        unsigned long long va = cand[tid], vb = cand[tid + 1024];
        // stages k=2..32: fully in registers (j<32 -> same warp)
#pragma unroll
        for (int k = 2; k <= 32; k <<= 1) {
#pragma unroll
            for (int j = k >> 1; j >= 1; j >>= 1) {
                bool lower = (tid & j) == 0;
                {
                    unsigned long long pa = __shfl_xor_sync(0xffffffffu, va, j);
                    bool dir = (tid & k) == 0;
                    va = (((dir == lower) ? (va > pa) : (va < pa))) ? va : pa;
                }
                {
                    unsigned long long pb = __shfl_xor_sync(0xffffffffu, vb, j);
                    bool dir = ((tid + 1024) & k) == 0;
                    vb = (((dir == lower) ? (vb > pb) : (vb < pb))) ? vb : pb;
                }
            }
        }
        cand[tid] = va; cand[tid + 1024] = vb;
        __syncthreads();
        for (int k = 64; k <= 2048; k <<= 1) {
            for (int j = k >> 1; j >= 32; j >>= 1) {
                for (int t2 = tid; t2 < 2048; t2 += 1024) {
                    int ixj = t2 ^ j;
                    if (ixj > t2) {
                        unsigned long long a = cand[t2], c = cand[ixj];
                        if (((t2 & k) == 0) ? (a < c) : (a > c)) { cand[t2] = c; cand[ixj] = a; }
                    }
                }
                __syncthreads();
            }
            va = cand[tid]; vb = cand[tid + 1024];
#pragma unroll
            for (int j = 16; j >= 1; j >>= 1) {
                bool lower = (tid & j) == 0;
                {
                    unsigned long long pa = __shfl_xor_sync(0xffffffffu, va, j);
                    bool dir = (tid & k) == 0;
                    va = (((dir == lower) ? (va > pa) : (va < pa))) ? va : pa;
                }
                {
                    unsigned long long pb = __shfl_xor_sync(0xffffffffu, vb, j);
                    bool dir = ((tid + 1024) & k) == 0;
                    vb = (((dir == lower) ? (vb > pb) : (vb < pb))) ? vb : pb;
                }
            }
            cand[tid] = va; cand[tid + 1024] = vb;
            __syncthreads();
        }
    } else {
        // ---- generic fallback (rare): plain smem bitonic up to 8192 ----
        int n2 = 2048; while (n2 < cnt) n2 <<= 1;
        for (int p = cnt + tid; p < n2; p += 1024) cand[p] = 0ull;
        __syncthreads();
        for (int k = 2; k <= n2; k <<= 1) {
            for (int j = k >> 1; j > 0; j >>= 1) {
                for (int t2 = tid; t2 < n2; t2 += 1024) {
                    int ixj = t2 ^ j;
                    if (ixj > t2) {
                        unsigned long long a = cand[t2], c = cand[ixj];
                        if (((t2 & k) == 0) ? (a < c) : (a > c)) { cand[t2] = c; cand[ixj] = a; }
                    }
                }
                __syncthreads();
            }
        }
    }

    // emit top-1024: score, label, xywh->xyxy (non-fused to match ref)
    {
        unsigned long long key = cand[tid];
        unsigned sb = (unsigned)(key >> 32);
        float score; int n;
        if (sb) { score = __uint_as_float(sb); n = (int)(0xFFFFFFFFu - (unsigned)key); }
        else    { score = -1.0f; n = 0; }
        const float* pr = pred + ((size_t)b * NN + n) * 25;
        float x = pr[0], y = pr[1], w = pr[2], h = pr[3];
        float hw = __fmul_rn(w, 0.5f), hh = __fmul_rn(h, 0.5f);
        int idx = b * KK + tid;
        g_tbox[idx] = make_float4(__fsub_rn(x, hw), __fsub_rn(y, hh),
                                  __fadd_rn(x, hw), __fadd_rn(y, hh));
        g_tsc[idx]  = score;
        g_tlb[idx]  = (int)g_lab[(size_t)b * NN + n];
    }
}

// ---------- kernel B2: pairwise IoU -> TRANSPOSED suppression mask (div-free fast path) ----------
// g_msk[b][w*1024+j] bit bi set <=> i=32w+bi < j AND iou(i,j) > thr
__global__ void k_iou() {
    __shared__ float sx1[KK], sy1[KK], sx2[KK], sy2[KK], sar[KK];
    int b = blockIdx.y;
    int tid = threadIdx.x;
    for (int q = tid; q < KK; q += 256) {
        float4 bx = g_tbox[b * KK + q];
        float off = __fmul_rn((float)g_tlb[b * KK + q], 4096.0f);
        // offsets applied BEFORE area: fp32 quantization at +label*4096 must match ref
        float ox1 = __fadd_rn(bx.x, off), oy1 = __fadd_rn(bx.y, off);
        float ox2 = __fadd_rn(bx.z, off), oy2 = __fadd_rn(bx.w, off);
        sx1[q] = ox1; sy1[q] = oy1; sx2[q] = ox2; sy2[q] = oy2;
        sar[q] = __fmul_rn(__fsub_rn(ox2, ox1), __fsub_rn(oy2, oy1));
    }
    __syncthreads();

    int jl = tid & 63;
    int j  = blockIdx.x * 64 + jl;
    int wq = tid >> 6;                       // 0..3 (warp-uniform)
    float jx1 = sx1[j], jy1 = sy1[j], jx2 = sx2[j], jy2 = sy2[j], aj = sar[j];
    unsigned* mcol = g_msk + (size_t)b * 32768 + j;

    for (int w = wq; w < 32; w += 4) {
        int imax = j - 32 * w;               // valid bi < imax
        int top = imax > 32 ? 32 : imax;
        unsigned bits = 0;
        for (int bi = 0; bi < top; bi++) {
            int i = 32 * w + bi;             // i < j guaranteed; broadcast smem reads
            float ltx = fmaxf(jx1, sx1[i]), lty = fmaxf(jy1, sy1[i]);
            float rbx = fminf(jx2, sx2[i]), rby = fminf(jy2, sy2[i]);
            float ww = fmaxf(__fsub_rn(rbx, ltx), 0.0f);
            float hh = fmaxf(__fsub_rn(rby, lty), 0.0f);
            float inter = __fmul_rn(ww, hh);
            float den = __fadd_rn(__fsub_rn(__fadd_rn(sar[i], aj), inter), 1e-9f);
            // margin compare: exact decision without div except in a ~1e-4 band
            float d = __fsub_rn(inter, __fmul_rn(IOU_T, den));
            float marg = __fmul_rn(den, 1e-4f);
            bool sup;
            if (fabsf(d) <= marg) sup = (inter / den) > IOU_T;   // rare exact IEEE path
            else                  sup = d > 0.0f;
            if (sup) bits |= (1u << bi);
        }
        if (top > 0) mcol[w * 1024] = bits;  // coalesced over j; skip empty upper-triangle words
    }
}

// ---------- kernel B3: forward-substitution greedy NMS + clip/filter + top-300 compaction ----------
__global__ void k_nms(const int* __restrict__ imw, const int* __restrict__ imh,
                      float* __restrict__ out) {
    extern __shared__ unsigned sh[];
    unsigned* cm    = sh;                    // 32768 words, [w][j] (lower triangle valid)
    unsigned* kws   = sh + 32768;            // 32 final keep words
    unsigned* wcnt  = sh + 32800;            // 32
    unsigned* wbal  = sh + 32832;            // 32
    int*      ctrl  = (int*)(sh + 32864);    // 4
    float4*   cbox  = (float4*)(sh + 32868); // 300 (32868*4 % 16 == 0)
    float*    cscore = (float*)(cbox + MAXDET);
    int*      clabel = (int*)(cscore + MAXDET);

    int b = blockIdx.x, tid = threadIdx.x;
    int lane = tid & 31, wid = tid >> 5;

    // load only lower-triangle mask words (w <= j/32); warp-uniform predicate keeps coalescing
    for (int k = tid; k < 32768; k += 1024) {
        int w = k >> 10, j = k & 1023;
        if (w <= (j >> 5)) cm[k] = g_msk[(size_t)b * 32768 + k];
    }
    float score = g_tsc[b * KK + tid];
    bool cnd = score > CONF_T;
    __syncthreads();

    // forward substitution: resolve keep words 0..31 in order (exact greedy)
    unsigned acc = 0;                                        // external suppression for j=tid
    unsigned mself = cm[wid * 1024 + tid] & ((1u << lane) - 1u);  // intra-word suppressors (i<j)
    for (int w = 0; w < 32; w++) {
        if (wid == w) {
            bool cn = cnd && (acc == 0u);
            unsigned kb = __ballot_sync(0xffffffffu, cn);
            for (int it = 0; it < 32; it++) {                // in-register Jacobi, depth-bounded
                bool k2 = cn && ((mself & kb) == 0u);
                unsigned nb = __ballot_sync(0xffffffffu, k2);
                if (nb == kb) break;
                kb = nb;
            }
            if (lane == 0) kws[w] = kb;
        }
        __syncthreads();
        if (w < wid) acc |= cm[w * 1024 + tid] & kws[w];
    }
    bool keep = (kws[wid] >> lane) & 1u;

    float fw = (float)(*imw), fh = (float)(*imh);
    float4 bx = g_tbox[b * KK + tid];
    float x1c = fminf(fmaxf(bx.x, 0.0f), fw);
    float y1c = fminf(fmaxf(bx.y, 0.0f), fh);
    float x2c = fminf(fmaxf(bx.z, 0.0f), fw);
    float y2c = fminf(fmaxf(bx.w, 0.0f), fh);
    float bw  = __fsub_rn(x2c, x1c);
    float bh2 = __fsub_rn(y2c, y1c);
    bool valid = keep && (bw > 0.0f) && (bh2 > 0.0f) && (bw >= 1.0f) && (bh2 >= 1.0f);

    unsigned vb = __ballot_sync(0xffffffffu, valid);
    if (lane == 0) { wcnt[wid] = __popc(vb); wbal[wid] = vb; }
    __syncthreads();
    if (tid == 0) {
        int acc2 = 0;
        for (int q = 0; q < 32; q++) { int c = wcnt[q]; wcnt[q] = acc2; acc2 += c; }
        ctrl[0] = acc2;
    }
    __syncthreads();
    if (valid) {
        int rank = wcnt[wid] + __popc(wbal[wid] & ((1u << lane) - 1u));
        if (rank < MAXDET) {
            cbox[rank]   = make_float4(x1c, y1c, x2c, y2c);
            cscore[rank] = score;
            clabel[rank] = g_tlb[b * KK + tid];
        }
    }
    __syncthreads();

    int total = ctrl[0]; if (total > MAXDET) total = MAXDET;
    if (tid < MAXDET) {
        float4 ob; float os, ol, ov;
        if (tid < total) { ob = cbox[tid]; os = cscore[tid]; ol = (float)clabel[tid]; ov = 1.0f; }
        else             { ob = make_float4(0, 0, 0, 0); os = 0.0f; ol = 0.0f; ov = 0.0f; }
        float* obox = out + ((size_t)b * MAXDET + tid) * 4;
        obox[0] = ob.x; obox[1] = ob.y; obox[2] = ob.z; obox[3] = ob.w;
        out[BB * MAXDET * 4 + b * MAXDET + tid] = os;   // det_scores
        out[BB * MAXDET * 5 + b * MAXDET + tid] = ol;   // det_labels (as f32)
        out[BB * MAXDET * 6 + b * MAXDET + tid] = ov;   // vm (as f32)
    }
}

extern "C" void kernel_launch(void* const* d_in, const int* in_sizes, int n_in,
                              void* d_out, int out_size) {
    const float* pred = (const float*)d_in[0];
    const int*   imh  = (const int*)d_in[1];
    const int*   imw  = (const int*)d_in[2];
    float* out = (float*)d_out;

    cudaFuncSetAttribute((const void*)k_topk,
                         cudaFuncAttributeMaxDynamicSharedMemorySize, 135488);
    cudaFuncSetAttribute((const void*)k_nms,
                         cudaFuncAttributeMaxDynamicSharedMemorySize, 138672);

    k_score<<<(BB * NN) / 256, 256>>>(pred);
    k_topk<<<BB, 1024, 135488>>>(pred);
    k_iou<<<dim3(16, BB), 256>>>();
    k_nms<<<BB, 1024, 138672>>>(imw, imh, out);
}

// round 4
// speedup vs baseline: 1.7917x; 1.7917x over previous
#include <cuda_runtime.h>
#include <cstdint>
#include <cstddef>

#define BB 32
#define NN 25200
#define NCC 20
#define KK 1024
#define MAXDET 300
#define CONF_T 0.001f
#define IOU_T 0.45f

// ---------- scratch (static device allocations; no cudaMalloc) ----------
__device__ float         g_conf[BB * NN];
__device__ unsigned char g_lab [BB * NN];
__device__ float4        g_tbox[BB * KK];
__device__ float         g_tsc [BB * KK];
__device__ int           g_tlb [BB * KK];
__device__ unsigned      g_msk [BB * KK * 32];   // TRANSPOSED mask: [b][w*1024+j], bit bi => i=32w+bi suppresses j (i<j)

// ---------- kernel A: scores + argmax labels (memory-bound full read, float4) ----------
__global__ void k_score(const float* __restrict__ pred) {
    __shared__ float s[256 * 25];
    size_t base4 = (size_t)blockIdx.x * 1600;           // 6400 floats = 1600 float4
    const float4* p4 = (const float4*)pred + base4;
    float4* s4 = (float4*)s;
    for (int k = threadIdx.x; k < 1600; k += 256) s4[k] = p4[k];
    __syncthreads();
    const float* row = s + threadIdx.x * 25;
    float obj  = row[4];
    float best = row[5];
    int   bl   = 0;
#pragma unroll
    for (int c = 1; c < NCC; c++) {
        float v = row[5 + c];
        if (v > best) { best = v; bl = c; }  // first-max like jnp.argmax
    }
    float conf = __fmul_rn(obj, best);
    size_t r = (size_t)blockIdx.x * 256 + threadIdx.x;
    g_conf[r] = conf;
    g_lab[r]  = (unsigned char)bl;
}

// ---------- kernel B1: exact stable top-1024 per batch (bucket select + hybrid bitonic) ----------
__global__ void k_topk(const float* __restrict__ pred) {
    extern __shared__ unsigned sh[];
    unsigned* hist  = sh;                 // 32768 words (128 KB)
    unsigned* chunk = sh + 32768;         // 1024 words
    int*      ctrl  = (int*)(sh + 33792); // 16 words: [0]=cstar [1]=T [2]=cnt
    unsigned* wsc   = sh + 33808;         // 64 words: warp totals + tails
    unsigned long long* cand = (unsigned long long*)sh;  // overlays hist (8192 keys)

    int b = blockIdx.x;
    int tid = threadIdx.x;
    int lane = tid & 31, wid = tid >> 5;
    const float* sc = g_conf + (size_t)b * NN;

    for (int k = tid; k < 32768; k += 1024) hist[k] = 0;
    if (tid < 16) ctrl[tid] = (tid == 0) ? -1 : 0;
    __syncthreads();

    // pass 1: histogram of float bits >>15 (positive scores are order-preserving)
    for (int n = tid; n < NN; n += 1024) {
        float v = sc[n];
        if (v > CONF_T) atomicAdd(&hist[__float_as_uint(v) >> 15], 1u);
    }
    __syncthreads();

    // per-thread chunk sums, then suffix-scan via warp shuffles
    unsigned sum = 0;
    {
        unsigned* hb = hist + tid * 32;
#pragma unroll
        for (int q = 0; q < 32; q++) sum += hb[q];
    }
    unsigned s = sum;
#pragma unroll
    for (int off = 1; off < 32; off <<= 1) {
        unsigned v = __shfl_down_sync(0xffffffffu, s, off);
        if (lane + off < 32) s += v;
    }
    if (lane == 0) wsc[wid] = s;          // warp total (suffix at lane 0)
    __syncthreads();
    if (wid == 0) {
        unsigned t = wsc[lane];
#pragma unroll
        for (int off = 1; off < 32; off <<= 1) {
            unsigned v = __shfl_down_sync(0xffffffffu, t, off);
            if (lane + off < 32) t += v;
        }
        unsigned tail = __shfl_down_sync(0xffffffffu, t, 1);
        if (lane == 31) tail = 0;
        wsc[32 + lane] = tail;            // sum of totals of warps > lane
    }
    __syncthreads();
    unsigned csuf = s + wsc[32 + wid];
    chunk[tid] = csuf;
    if (csuf >= KK) atomicMax(&ctrl[0], tid);
    __syncthreads();
    if (tid == 0) {
        int cs = ctrl[0];
        int T = 0;
        if (cs >= 0) {
            unsigned running = (cs < 1023) ? chunk[cs + 1] : 0u;
            for (int bk = cs * 32 + 31; bk >= cs * 32; bk--) {
                running += hist[bk];
                if (running >= KK) { T = bk; break; }
            }
        }
        ctrl[1] = T;
        ctrl[2] = 0;
    }
    __syncthreads();
    unsigned T = (unsigned)ctrl[1];
    __syncthreads();   // hist reads done; cand may now overlay hist

    // pass 2: collect candidates with stable-tiebreak keys
    for (int n = tid; n < NN; n += 1024) {
        float v = sc[n];
        if (v > CONF_T && (__float_as_uint(v) >> 15) >= T) {
            int p = atomicAdd(&ctrl[2], 1);
            if (p < 8192)
                cand[p] = ((unsigned long long)__float_as_uint(v) << 32)
                        | (unsigned long long)(0xFFFFFFFFu - (unsigned)n);
        }
    }
    __syncthreads();
    int cnt = ctrl[2]; if (cnt > 8192) cnt = 8192;

    if (cnt <= 2048) {
        // ---- hybrid bitonic sort of 2048 keys, descending ----
        for (int p = cnt + tid; p < 2048; p += 1024) cand[p] = 0ull;
        __syncthreads();
        unsigned long long va = cand[tid], vb = cand[tid + 1024];
#pragma unroll
        for (int k = 2; k <= 32; k <<= 1) {
#pragma unroll
            for (int j = k >> 1; j >= 1; j >>= 1) {
                bool lower = (tid & j) == 0;
                {
                    unsigned long long pa = __shfl_xor_sync(0xffffffffu, va, j);
                    bool dir = (tid & k) == 0;
                    va = (((dir == lower) ? (va > pa) : (va < pa))) ? va : pa;
                }
                {
                    unsigned long long pb = __shfl_xor_sync(0xffffffffu, vb, j);
                    bool dir = ((tid + 1024) & k) == 0;
                    vb = (((dir == lower) ? (vb > pb) : (vb < pb))) ? vb : pb;
                }
            }
        }
        cand[tid] = va; cand[tid + 1024] = vb;
        __syncthreads();
        for (int k = 64; k <= 2048; k <<= 1) {
            for (int j = k >> 1; j >= 32; j >>= 1) {
                for (int t2 = tid; t2 < 2048; t2 += 1024) {
                    int ixj = t2 ^ j;
                    if (ixj > t2) {
                        unsigned long long a = cand[t2], c = cand[ixj];
                        if (((t2 & k) == 0) ? (a < c) : (a > c)) { cand[t2] = c; cand[ixj] = a; }
                    }
                }
                __syncthreads();
            }
            va = cand[tid]; vb = cand[tid + 1024];
#pragma unroll
            for (int j = 16; j >= 1; j >>= 1) {
                bool lower = (tid & j) == 0;
                {
                    unsigned long long pa = __shfl_xor_sync(0xffffffffu, va, j);
                    bool dir = (tid & k) == 0;
                    va = (((dir == lower) ? (va > pa) : (va < pa))) ? va : pa;
                }
                {
                    unsigned long long pb = __shfl_xor_sync(0xffffffffu, vb, j);
                    bool dir = ((tid + 1024) & k) == 0;
                    vb = (((dir == lower) ? (vb > pb) : (vb < pb))) ? vb : pb;
                }
            }
            cand[tid] = va; cand[tid + 1024] = vb;
            __syncthreads();
        }
    } else {
        // ---- generic fallback (rare): plain smem bitonic up to 8192 ----
        int n2 = 2048; while (n2 < cnt) n2 <<= 1;
        for (int p = cnt + tid; p < n2; p += 1024) cand[p] = 0ull;
        __syncthreads();
        for (int k = 2; k <= n2; k <<= 1) {
            for (int j = k >> 1; j > 0; j >>= 1) {
                for (int t2 = tid; t2 < n2; t2 += 1024) {
                    int ixj = t2 ^ j;
                    if (ixj > t2) {
                        unsigned long long a = cand[t2], c = cand[ixj];
                        if (((t2 & k) == 0) ? (a < c) : (a > c)) { cand[t2] = c; cand[ixj] = a; }
                    }
                }
                __syncthreads();
            }
        }
    }

    // emit top-1024: score, label, xywh->xyxy (non-fused to match ref)
    {
        unsigned long long key = cand[tid];
        unsigned sb = (unsigned)(key >> 32);
        float score; int n;
        if (sb) { score = __uint_as_float(sb); n = (int)(0xFFFFFFFFu - (unsigned)key); }
        else    { score = -1.0f; n = 0; }
        const float* pr = pred + ((size_t)b * NN + n) * 25;
        float x = pr[0], y = pr[1], w = pr[2], h = pr[3];
        float hw = __fmul_rn(w, 0.5f), hh = __fmul_rn(h, 0.5f);
        int idx = b * KK + tid;
        g_tbox[idx] = make_float4(__fsub_rn(x, hw), __fsub_rn(y, hh),
                                  __fadd_rn(x, hw), __fadd_rn(y, hh));
        g_tsc[idx]  = score;
        g_tlb[idx]  = (int)g_lab[(size_t)b * NN + n];
    }
}

// ---------- kernel B2: pairwise IoU -> TRANSPOSED mask, load-balanced strip pairing ----------
// Block (wp, b) handles word-strips w=wp and w=31-wp: combined j-count is constant (1056).
// g_msk[b][w*1024+j] bit bi set <=> i=32w+bi < j AND iou(i,j) > thr. top==0 words never written
// (k_nms masks the self word), all other needed words written exactly once.
__global__ void k_iou() {
    __shared__ float ix1[64], iy1[64], ix2[64], iy2[64], iar[64];
    int b = blockIdx.y, wp = blockIdx.x, tid = threadIdx.x;

    if (tid < 64) {
        int strip = (tid < 32) ? wp : (31 - wp);
        int i = strip * 32 + (tid & 31);
        float4 bx = g_tbox[b * KK + i];
        float off = __fmul_rn((float)g_tlb[b * KK + i], 4096.0f);
        // offsets applied BEFORE area: fp32 quantization at +label*4096 must match ref
        float ox1 = __fadd_rn(bx.x, off), oy1 = __fadd_rn(bx.y, off);
        float ox2 = __fadd_rn(bx.z, off), oy2 = __fadd_rn(bx.w, off);
        ix1[tid] = ox1; iy1[tid] = oy1; ix2[tid] = ox2; iy2[tid] = oy2;
        iar[tid] = __fmul_rn(__fsub_rn(ox2, ox1), __fsub_rn(oy2, oy1));
    }
    __syncthreads();

#pragma unroll
    for (int half = 0; half < 2; half++) {
        int w = half ? (31 - wp) : wp;
        int sbase = half * 32;
        for (int j = 32 * w + tid; j < 1024; j += 256) {
            float4 bx = g_tbox[b * KK + j];
            float off = __fmul_rn((float)g_tlb[b * KK + j], 4096.0f);
            float jx1 = __fadd_rn(bx.x, off), jy1 = __fadd_rn(bx.y, off);
            float jx2 = __fadd_rn(bx.z, off), jy2 = __fadd_rn(bx.w, off);
            float aj  = __fmul_rn(__fsub_rn(jx2, jx1), __fsub_rn(jy2, jy1));
            int top = j - 32 * w; if (top > 32) top = 32;
            unsigned bits = 0;
            for (int bi = 0; bi < top; bi++) {   // smem broadcast reads
                float ltx = fmaxf(jx1, ix1[sbase + bi]), lty = fmaxf(jy1, iy1[sbase + bi]);
                float rbx = fminf(jx2, ix2[sbase + bi]), rby = fminf(jy2, iy2[sbase + bi]);
                float ww = fmaxf(__fsub_rn(rbx, ltx), 0.0f);
                float hh = fmaxf(__fsub_rn(rby, lty), 0.0f);
                float inter = __fmul_rn(ww, hh);
                float den = __fadd_rn(__fsub_rn(__fadd_rn(iar[sbase + bi], aj), inter), 1e-9f);
                // margin compare: exact decision without div except in a ~1e-4 band
                float d = __fsub_rn(inter, __fmul_rn(IOU_T, den));
                float marg = __fmul_rn(den, 1e-4f);
                bool sup;
                if (fabsf(d) <= marg) sup = (inter / den) > IOU_T;   // rare exact IEEE path
                else                  sup = d > 0.0f;
                if (sup) bits |= (1u << bi);
            }
            if (top > 0) g_msk[(size_t)b * 32768 + w * 1024 + j] = bits;  // coalesced over j
        }
    }
}

// ---------- kernel B3: Jacobi-fixpoint greedy NMS + clip/filter + top-300 compaction ----------
__global__ void k_nms(const int* __restrict__ imw, const int* __restrict__ imh,
                      float* __restrict__ out) {
    extern __shared__ unsigned sh[];
    unsigned* cm    = sh;                    // 32768 words, [w][j] (lower triangle valid)
    unsigned* kwsA  = sh + 32768;            // 32
    unsigned* kwsB  = sh + 32800;            // 32
    unsigned* wcnt  = sh + 32832;            // 32
    unsigned* wbal  = sh + 32864;            // 32
    int*      ctrl  = (int*)(sh + 32896);    // 4
    float4*   cbox  = (float4*)(sh + 32900); // 300 (32900*4 % 16 == 0)
    float*    cscore = (float*)(cbox + MAXDET);
    int*      clabel = (int*)(cscore + MAXDET);

    int b = blockIdx.x, tid = threadIdx.x;
    int lane = tid & 31, wid = tid >> 5;

    // vectorized lower-triangle mask load (4-aligned j groups share the same w, j>>5)
    for (int base = tid * 4; base < 32768; base += 4096) {
        int w = base >> 10, j0 = base & 1023;
        if (w <= (j0 >> 5))
            *(uint4*)(cm + base) = *(const uint4*)(g_msk + (size_t)b * 32768 + base);
    }
    float score = g_tsc[b * KK + tid];
    bool cnd = score > CONF_T;
    unsigned cbal = __ballot_sync(0xffffffffu, cnd);
    if (lane == 0) kwsA[wid] = cbal;
    __syncthreads();

    // Jacobi fixpoint: keep[j] = cand[j] & !exists(i<j: sup(i,j) & keep[i])
    // converges to the unique greedy solution; self word masked to lane-lower bits
    unsigned* cur = kwsA;
    unsigned* nxt = kwsB;
    unsigned mself = cm[wid * 1024 + tid] & ((1u << lane) - 1u);
    for (int it = 0; it < 1025; it++) {
        unsigned sup = mself & cur[wid];
        for (int w = 0; w < wid; w++)
            sup |= cm[w * 1024 + tid] & cur[w];  // lanes->consecutive j: conflict-free; cur[w] broadcast
        bool nk = cnd && (sup == 0u);
        unsigned nb = __ballot_sync(0xffffffffu, nk);
        if (lane == 0) nxt[wid] = nb;
        int changed = __syncthreads_or((int)(nb != cur[wid]));
        if (!changed) break;
        unsigned* t = cur; cur = nxt; nxt = t;
    }

    bool keep = (cur[wid] >> lane) & 1u;
    float fw = (float)(*imw), fh = (float)(*imh);
    float4 bx = g_tbox[b * KK + tid];
    float x1c = fminf(fmaxf(bx.x, 0.0f), fw);
    float y1c = fminf(fmaxf(bx.y, 0.0f), fh);
    float x2c = fminf(fmaxf(bx.z, 0.0f), fw);
    float y2c = fminf(fmaxf(bx.w, 0.0f), fh);
    float bw  = __fsub_rn(x2c, x1c);
    float bh2 = __fsub_rn(y2c, y1c);
    bool valid = keep && (bw > 0.0f) && (bh2 > 0.0f) && (bw >= 1.0f) && (bh2 >= 1.0f);

    unsigned vb = __ballot_sync(0xffffffffu, valid);
    if (lane == 0) { wcnt[wid] = __popc(vb); wbal[wid] = vb; }
    __syncthreads();
    if (tid == 0) {
        int acc2 = 0;
        for (int q = 0; q < 32; q++) { int c = wcnt[q]; wcnt[q] = acc2; acc2 += c; }
        ctrl[0] = acc2;
    }
    __syncthreads();
    if (valid) {
        int rank = wcnt[wid] + __popc(wbal[wid] & ((1u << lane) - 1u));
        if (rank < MAXDET) {
            cbox[rank]   = make_float4(x1c, y1c, x2c, y2c);
            cscore[rank] = score;
            clabel[rank] = g_tlb[b * KK + tid];
        }
    }
    __syncthreads();

    int total = ctrl[0]; if (total > MAXDET) total = MAXDET;
    if (tid < MAXDET) {
        float4 ob; float os, ol, ov;
        if (tid < total) { ob = cbox[tid]; os = cscore[tid]; ol = (float)clabel[tid]; ov = 1.0f; }
        else             { ob = make_float4(0, 0, 0, 0); os = 0.0f; ol = 0.0f; ov = 0.0f; }
        float* obox = out + ((size_t)b * MAXDET + tid) * 4;
        obox[0] = ob.x; obox[1] = ob.y; obox[2] = ob.z; obox[3] = ob.w;
        out[BB * MAXDET * 4 + b * MAXDET + tid] = os;   // det_scores
        out[BB * MAXDET * 5 + b * MAXDET + tid] = ol;   // det_labels (as f32)
        out[BB * MAXDET * 6 + b * MAXDET + tid] = ov;   // vm (as f32)
    }
}

extern "C" void kernel_launch(void* const* d_in, const int* in_sizes, int n_in,
                              void* d_out, int out_size) {
    const float* pred = (const float*)d_in[0];
    const int*   imh  = (const int*)d_in[1];
    const int*   imw  = (const int*)d_in[2];
    float* out = (float*)d_out;

    cudaFuncSetAttribute((const void*)k_topk,
                         cudaFuncAttributeMaxDynamicSharedMemorySize, 135488);
    cudaFuncSetAttribute((const void*)k_nms,
                         cudaFuncAttributeMaxDynamicSharedMemorySize, 138800);

    k_score<<<(BB * NN) / 256, 256>>>(pred);
    k_topk<<<BB, 1024, 135488>>>(pred);
    k_iou<<<dim3(16, BB), 256>>>();
    k_nms<<<BB, 1024, 138800>>>(imw, imh, out);
}